// round 11
// baseline (speedup 1.0000x reference)
#include <cuda_runtime.h>
#include <cooperative_groups.h>
namespace cg = cooperative_groups;

#define F 256
#define F4 (F / 4)                   // 64 float4 per row
#define TOTAL_ROWS (32 * 4096)       // B*T = 131072
#define NBLOCKS 512
#define NTHREADS 256
#define ROWS_PER_BLOCK (TOTAL_ROWS / NBLOCKS)   // 256 rows = 256 KB territory
#define EPS 1e-5f

// Scratch (no cudaMalloc). Fully overwritten before read on every call ->
// deterministic, graph-replay safe, no carried state.
__device__ float g_psum[NBLOCKS * F];
__device__ float g_psq [NBLOCKS * F];
__device__ float g_pcnt[NBLOCKS];
__device__ float g_scale[F];
__device__ float g_bias[F];

// ---------------------------------------------------------------------------
// ONE cooperative kernel, three phases separated by grid.sync():
//  A) per-block ballot-compaction of its 256-row territory + masked-row
//     gather (batches of 8 LDG.128, MLP=8, __ldcg fills L2) -> partials via
//     coalesced plain stores (no atomics).
//  B) blocks 0..7 reduce the 512 partial sets + finalize scale/bias.
//  C) every block applies ITS OWN territory: the masked rows it reads are
//     the exact lines it loaded in phase A -> L2 hits, cutting ~64 MB DRAM.
// ---------------------------------------------------------------------------
__global__ void __launch_bounds__(NTHREADS, 4)
fused_kernel(const float* __restrict__ x, const int* __restrict__ mask,
             const float* __restrict__ gamma, const float* __restrict__ beta,
             float* __restrict__ out) {
    cg::grid_group grid = cg::this_grid();

    const int tid  = threadIdx.x;
    const int f4   = tid & 63;       // float4 column within row
    const int sub  = tid >> 6;       // row slot 0..3
    const int lane = tid & 31;
    const int wrp  = tid >> 5;       // 0..7
    const int row0 = blockIdx.x * ROWS_PER_BLOCK;

    const float4* __restrict__ x4 = (const float4*)x;

    __shared__ int   s_list[ROWS_PER_BLOCK];
    __shared__ int   s_wbase[8];
    __shared__ int   s_cnt;
    __shared__ float4 s_sum[NTHREADS];
    __shared__ float4 s_sq[NTHREADS];

    // ================= Phase A: compaction + masked gather =================
    const bool p = mask[row0 + tid] > 0;          // 1 row per thread
    const unsigned bal = __ballot_sync(0xffffffffu, p);
    if (lane == 0) s_wbase[wrp] = __popc(bal);
    __syncthreads();
    if (tid == 0) {
        int run = 0;
#pragma unroll
        for (int k = 0; k < 8; ++k) { int c = s_wbase[k]; s_wbase[k] = run; run += c; }
        s_cnt = run;
    }
    __syncthreads();
    if (p) s_list[s_wbase[wrp] + __popc(bal & ((1u << lane) - 1u))] = row0 + tid;
    __syncthreads();

    const int cnt = s_cnt;

    float4 acc  = make_float4(0.f, 0.f, 0.f, 0.f);
    float4 acc2 = make_float4(0.f, 0.f, 0.f, 0.f);

#pragma unroll 1
    for (int base = 0; base < cnt; base += 32) {   // 32 rows in flight / iter
        int   row[8];
        float w[8];
#pragma unroll
        for (int u = 0; u < 8; ++u) {
            const int k = base + u * 4 + sub;
            const bool val = k < cnt;
            row[u] = val ? s_list[k] : s_list[0];  // smem broadcast
            w[u]   = val ? 1.0f : 0.0f;
        }
        float4 v[8];
#pragma unroll
        for (int u = 0; u < 8; ++u)
            v[u] = __ldcg(&x4[(size_t)row[u] * F4 + f4]);   // fill L2 (phase C reuse)
#pragma unroll
        for (int u = 0; u < 8; ++u) {
            const float wx = w[u];
            acc.x  = fmaf(v[u].x, wx, acc.x);
            acc.y  = fmaf(v[u].y, wx, acc.y);
            acc.z  = fmaf(v[u].z, wx, acc.z);
            acc.w  = fmaf(v[u].w, wx, acc.w);
            acc2.x = fmaf(v[u].x * wx, v[u].x, acc2.x);
            acc2.y = fmaf(v[u].y * wx, v[u].y, acc2.y);
            acc2.z = fmaf(v[u].z * wx, v[u].z, acc2.z);
            acc2.w = fmaf(v[u].w * wx, v[u].w, acc2.w);
        }
    }

    // intra-block reduction across the 4 row-slots, then plain stores
    s_sum[tid] = acc;
    s_sq[tid]  = acc2;
    __syncthreads();
    if (sub == 0) {
#pragma unroll
        for (int k = 1; k < 4; k++) {
            float4 a = s_sum[tid + 64 * k];
            float4 b = s_sq[tid + 64 * k];
            acc.x += a.x; acc.y += a.y; acc.z += a.z; acc.w += a.w;
            acc2.x += b.x; acc2.y += b.y; acc2.z += b.z; acc2.w += b.w;
        }
        s_sum[f4] = acc;
        s_sq[f4]  = acc2;
    }
    __syncthreads();
    {
        const float* rs = (const float*)s_sum;
        const float* rq = (const float*)s_sq;
        const size_t o = (size_t)blockIdx.x * F + tid;
        g_psum[o] = rs[tid];
        g_psq[o]  = rq[tid];
        if (tid == 0) g_pcnt[blockIdx.x] = (float)cnt;
    }

    grid.sync();

    // ================= Phase B: reduce + finalize (blocks 0..7) =============
    if (blockIdx.x < 8) {
        const int fl = tid & 31;
        const int j  = tid >> 5;                 // 0..7, slice of 64 partials
        const int f  = blockIdx.x * 32 + fl;

        float sum = 0.f, sq = 0.f;
#pragma unroll 1
        for (int b = j * 64; b < (j + 1) * 64; b += 8) {
            float a0[8], a1[8];
#pragma unroll
            for (int u = 0; u < 8; ++u) {
                a0[u] = g_psum[(size_t)(b + u) * F + f];
                a1[u] = g_psq [(size_t)(b + u) * F + f];
            }
#pragma unroll
            for (int u = 0; u < 8; ++u) { sum += a0[u]; sq += a1[u]; }
        }

        float c = g_pcnt[tid] + g_pcnt[tid + 256];
#pragma unroll
        for (int off = 16; off > 0; off >>= 1)
            c += __shfl_down_sync(0xffffffffu, c, off);

        float* s_f = (float*)s_sum;              // reuse smem
        float* s_g = (float*)s_sq;
        __shared__ float s_cw[8];
        __shared__ float s_total;
        s_f[tid] = sum;
        s_g[tid] = sq;
        if (lane == 0) s_cw[wrp] = c;
        __syncthreads();
        if (tid == 0) {
            float t = 0.f;
#pragma unroll
            for (int k = 0; k < 8; ++k) t += s_cw[k];
            s_total = t;
        }
        __syncthreads();
        if (j == 0) {
#pragma unroll
            for (int k = 1; k < 8; ++k) {
                sum += s_f[fl + 32 * k];
                sq  += s_g[fl + 32 * k];
            }
            const float cntf = s_total;
            const float mean = sum / cntf;
            const float var  = sq / cntf - mean * mean;
            const float s    = rsqrtf(var + EPS) * gamma[f];
            g_scale[f] = s;
            g_bias[f]  = beta[f] - mean * s;
        }
    }

    grid.sync();

    // ================= Phase C: apply own territory =========================
    const float4 sc = ((const float4*)g_scale)[f4];
    const float4 bi = ((const float4*)g_bias)[f4];
    float4* __restrict__ out4 = (float4*)out;

#pragma unroll 1
    for (int g0 = 0; g0 < ROWS_PER_BLOCK / 4; g0 += 8) {   // 32 rows / iter
        int    rw[8];
        float4 v[8];
#pragma unroll
        for (int u = 0; u < 8; ++u) {
            const int row = row0 + (g0 + u) * 4 + sub;
            rw[u] = mask[row];                               // L1/L2 hit
            v[u]  = x4[(size_t)row * F4 + f4];               // L2 hit if masked
        }
#pragma unroll
        for (int u = 0; u < 8; ++u) {
            float4 r;
            r.x = fmaf(v[u].x, sc.x, bi.x);
            r.y = fmaf(v[u].y, sc.y, bi.y);
            r.z = fmaf(v[u].z, sc.z, bi.z);
            r.w = fmaf(v[u].w, sc.w, bi.w);
            const bool m = rw[u] > 0;
            if (m) v[u] = r;                                 // warp-uniform select
            const int row = row0 + (g0 + u) * 4 + sub;
            __stcs(&out4[(size_t)row * F4 + f4], v[u]);
        }
    }
}

// ---------------------------------------------------------------------------
extern "C" void kernel_launch(void* const* d_in, const int* in_sizes, int n_in,
                              void* d_out, int out_size) {
    const float* x     = (const float*)d_in[0];
    const int*   mask  = (const int*)d_in[1];
    const float* gamma = (const float*)d_in[2];
    const float* beta  = (const float*)d_in[3];
    float*       out   = (float*)d_out;

    void* args[] = { (void*)&x, (void*)&mask, (void*)&gamma, (void*)&beta,
                     (void*)&out };
    cudaLaunchCooperativeKernel((const void*)fused_kernel,
                                dim3(NBLOCKS), dim3(NTHREADS),
                                args, 0, (cudaStream_t)0);
}

// round 14
// speedup vs baseline: 1.2655x; 1.2655x over previous
#include <cuda_runtime.h>

#define F 256
#define F4 (F / 4)                   // 64 float4 per row
#define TOTAL_ROWS (32 * 4096)       // B*T = 131072
#define STATS_BLOCKS 1024
#define ROWS_PER_BLOCK 128           // stats block territory
#define STATS_THREADS 256
#define RED_BLOCKS 8
#define APPLY_BLOCKS 8192            // 8192 blocks x 256 thr x 4 float4
#define APPLY_PER_THREAD 4
#define EPS 1e-5f

// Scratch (no cudaMalloc). Fully overwritten before read on every call ->
// deterministic, graph-replay safe, no init kernel, no carried state.
// NOTE: module globals are only ever accessed as SCALAR floats (no float4
// casts of globals anywhere — suspected source of the R12/R13 misaligned
// address fault).
__device__ float g_psum[STATS_BLOCKS * F];
__device__ float g_psq [STATS_BLOCKS * F];
__device__ float g_pcnt[STATS_BLOCKS];
__device__ float g_scale[F];
__device__ float g_bias[F];

// ---------------------------------------------------------------------------
// Kernel 1: per-feature partial sum / sumsq over ONLY masked rows, with
// in-block ballot compaction (byte-exact R10 version — passed twice).
// ---------------------------------------------------------------------------
__global__ void __launch_bounds__(STATS_THREADS)
stats_kernel(const float* __restrict__ x, const int* __restrict__ mask) {
    const int tid  = threadIdx.x;
    const int f4   = tid & 63;       // float4 column within row
    const int sub  = tid >> 6;       // row slot 0..3
    const int row0 = blockIdx.x * ROWS_PER_BLOCK;

    __shared__ int   s_rows[ROWS_PER_BLOCK];
    __shared__ int   s_wbase[5];

    if (tid < ROWS_PER_BLOCK) {
        const int  lane = tid & 31;
        const int  w    = tid >> 5;              // warp-slice 0..3
        const bool p    = mask[row0 + tid] > 0;
        const unsigned bal = __ballot_sync(0xffffffffu, p);
        if (lane == 0) s_wbase[w + 1] = __popc(bal);
        if (tid == 0)  s_wbase[0] = 0;
        __syncwarp();
        if (p) {
            const int inwarp = __popc(bal & ((1u << lane) - 1u));
            s_rows[w * 32 + inwarp] = row0 + tid;
        }
        if (lane == 0) s_wbase[w + 1] = __popc(bal);
    }
    __syncthreads();

    __shared__ int s_list[ROWS_PER_BLOCK];
    __shared__ int s_cnt;
    if (tid == 0) {
        int run = 0;
#pragma unroll
        for (int k = 0; k < 4; ++k) { int c = s_wbase[k + 1]; s_wbase[k] = run; run += c; }
        s_cnt = run;
        s_wbase[4] = run;
    }
    __syncthreads();
    if (tid < ROWS_PER_BLOCK) {
        const int w = tid >> 5, lane = tid & 31;
        const int segc = s_wbase[w + 1] - s_wbase[w];
        if (lane < segc) s_list[s_wbase[w] + lane] = s_rows[w * 32 + lane];
    }
    __syncthreads();

    const int cnt = s_cnt;
    const float4* __restrict__ x4 = (const float4*)x;

    float4 acc  = make_float4(0.f, 0.f, 0.f, 0.f);
    float4 acc2 = make_float4(0.f, 0.f, 0.f, 0.f);

#pragma unroll 1
    for (int base = 0; base < cnt; base += 32) {
        int   row[8];
        float w[8];
#pragma unroll
        for (int u = 0; u < 8; ++u) {
            const int k = base + u * 4 + sub;
            const bool val = k < cnt;
            row[u] = val ? s_list[k] : s_list[0];   // smem broadcast
            w[u]   = val ? 1.0f : 0.0f;
        }
        float4 v[8];
#pragma unroll
        for (int u = 0; u < 8; ++u)
            v[u] = __ldcg(&x4[(size_t)row[u] * F4 + f4]);   // fill L2 for apply
#pragma unroll
        for (int u = 0; u < 8; ++u) {
            const float wx = w[u];
            acc.x  = fmaf(v[u].x, wx, acc.x);
            acc.y  = fmaf(v[u].y, wx, acc.y);
            acc.z  = fmaf(v[u].z, wx, acc.z);
            acc.w  = fmaf(v[u].w, wx, acc.w);
            acc2.x = fmaf(v[u].x * wx, v[u].x, acc2.x);
            acc2.y = fmaf(v[u].y * wx, v[u].y, acc2.y);
            acc2.z = fmaf(v[u].z * wx, v[u].z, acc2.z);
            acc2.w = fmaf(v[u].w * wx, v[u].w, acc2.w);
        }
    }

    __shared__ float4 s_sum[256];
    __shared__ float4 s_sq[256];
    s_sum[tid] = acc;
    s_sq[tid]  = acc2;
    __syncthreads();

    if (sub == 0) {
#pragma unroll
        for (int k = 1; k < 4; k++) {
            float4 a = s_sum[tid + 64 * k];
            float4 b = s_sq[tid + 64 * k];
            acc.x += a.x; acc.y += a.y; acc.z += a.z; acc.w += a.w;
            acc2.x += b.x; acc2.y += b.y; acc2.z += b.z; acc2.w += b.w;
        }
        s_sum[f4] = acc;
        s_sq[f4]  = acc2;
    }
    __syncthreads();

    const float* rs = (const float*)s_sum;   // smem float4 arrays: aligned by type
    const float* rq = (const float*)s_sq;
    const size_t o = (size_t)blockIdx.x * F + tid;
    g_psum[o] = rs[tid];
    g_psq[o]  = rq[tid];
    if (tid == 0) g_pcnt[blockIdx.x] = (float)cnt;
}

// ---------------------------------------------------------------------------
// Kernel 2: parallel reduce + finalize (byte-exact R10 version).
// ---------------------------------------------------------------------------
__global__ void __launch_bounds__(256)
reduce_finalize_kernel(const float* __restrict__ gamma,
                       const float* __restrict__ beta) {
    const int tid = threadIdx.x;
    const int fl  = tid & 31;
    const int j   = tid >> 5;                  // 0..7
    const int f   = blockIdx.x * 32 + fl;

    float sum = 0.f, sq = 0.f;
#pragma unroll 1
    for (int b = j * 128; b < (j + 1) * 128; b += 8) {
        float a0[8], a1[8];
#pragma unroll
        for (int u = 0; u < 8; ++u) {
            a0[u] = g_psum[(size_t)(b + u) * F + f];
            a1[u] = g_psq [(size_t)(b + u) * F + f];
        }
#pragma unroll
        for (int u = 0; u < 8; ++u) { sum += a0[u]; sq += a1[u]; }
    }

    float c = g_pcnt[tid] + g_pcnt[tid + 256] + g_pcnt[tid + 512] + g_pcnt[tid + 768];
#pragma unroll
    for (int off = 16; off > 0; off >>= 1)
        c += __shfl_down_sync(0xffffffffu, c, off);

    __shared__ float s_sum[256];
    __shared__ float s_sq[256];
    __shared__ float s_cw[8];
    __shared__ float s_total;
    s_sum[tid] = sum;
    s_sq[tid]  = sq;
    if ((tid & 31) == 0) s_cw[tid >> 5] = c;
    __syncthreads();
    if (tid == 0) {
        float t = 0.f;
#pragma unroll
        for (int k = 0; k < 8; ++k) t += s_cw[k];
        s_total = t;
    }
    __syncthreads();

    if (j == 0) {
#pragma unroll
        for (int k = 1; k < 8; ++k) {
            sum += s_sum[fl + 32 * k];
            sq  += s_sq[fl + 32 * k];
        }
        const float cnt  = s_total;
        const float mean = sum / cnt;
        const float var  = sq / cnt - mean * mean;
        const float s    = rsqrtf(var + EPS) * gamma[f];
        g_scale[f] = s;
        g_bias[f]  = beta[f] - mean * s;
    }
}

// ---------------------------------------------------------------------------
// Kernel 3: apply, BATCHED 4 float4/thread (stride 256 keeps f4 invariant),
// reversed block order. Scale/bias loaded as SCALAR floats — no float4 cast
// of module globals anywhere in this kernel.
// ---------------------------------------------------------------------------
__global__ void __launch_bounds__(256) apply_kernel(const float* __restrict__ x,
                                                    const int*   __restrict__ mask,
                                                    float*       __restrict__ out) {
    const int tid = threadIdx.x;
    const unsigned bid = (unsigned)(APPLY_BLOCKS - 1) - blockIdx.x;  // reverse
    const size_t base = (size_t)bid * (256 * APPLY_PER_THREAD) + tid;
    const int f4 = tid & 63;

    const float4* __restrict__ x4 = (const float4*)x;
    float4* __restrict__ out4 = (float4*)out;

    // scalar loads (broadcast, L1-cached)
    const float scx = g_scale[f4 * 4 + 0];
    const float scy = g_scale[f4 * 4 + 1];
    const float scz = g_scale[f4 * 4 + 2];
    const float scw = g_scale[f4 * 4 + 3];
    const float bix = g_bias [f4 * 4 + 0];
    const float biy = g_bias [f4 * 4 + 1];
    const float biz = g_bias [f4 * 4 + 2];
    const float biw = g_bias [f4 * 4 + 3];

    float4 v[APPLY_PER_THREAD];
    int    m[APPLY_PER_THREAD];
#pragma unroll
    for (int u = 0; u < APPLY_PER_THREAD; ++u) {
        const size_t i = base + (size_t)u * 256;
        m[u] = mask[i >> 6];             // warp-broadcast L1/L2 hit
        v[u] = __ldcs(&x4[i]);
    }
#pragma unroll
    for (int u = 0; u < APPLY_PER_THREAD; ++u) {
        float4 r;
        r.x = fmaf(v[u].x, scx, bix);
        r.y = fmaf(v[u].y, scy, biy);
        r.z = fmaf(v[u].z, scz, biz);
        r.w = fmaf(v[u].w, scw, biw);
        if (m[u] > 0) v[u] = r;          // warp-uniform select
    }
#pragma unroll
    for (int u = 0; u < APPLY_PER_THREAD; ++u) {
        const size_t i = base + (size_t)u * 256;
        __stcs(&out4[i], v[u]);
    }
}

// ---------------------------------------------------------------------------
extern "C" void kernel_launch(void* const* d_in, const int* in_sizes, int n_in,
                              void* d_out, int out_size) {
    const float* x     = (const float*)d_in[0];
    const int*   mask  = (const int*)d_in[1];
    const float* gamma = (const float*)d_in[2];
    const float* beta  = (const float*)d_in[3];
    float*       out   = (float*)d_out;

    stats_kernel<<<STATS_BLOCKS, STATS_THREADS>>>(x, mask);
    reduce_finalize_kernel<<<RED_BLOCKS, 256>>>(gamma, beta);
    apply_kernel<<<APPLY_BLOCKS, 256>>>(x, mask, out);
}